// round 8
// baseline (speedup 1.0000x reference)
#include <cuda_runtime.h>
#include <cstdint>

// Depthwise 9x9 conv, stride 1, pad 4. X:(32,64,256,256) fp32, one shared kernel.
// R7: widen LDS latency margin + strip non-FMA issue slots.
//  - depth-3 rotating pipeline regs P[3] (compile-time %3 indexing, renamed by
//    ptxas -> zero copy MOVs); each LDS leads its consumer by ~20 issue slots.
//  - k coeffs pre-packed {k,k} into a __device__ array by a tiny pre-kernel:
//    per-tap setup = 9 uniform LDG.64 (no LDC+MOV pairs).
//  - unchanged from R6: 128-thr CTA, thread = 2 cols x 16 rows, 64x64 tile,
//    dual shifted stride-72 smem copies (any parity window = one LDS.64,
//    conflict-free), runtime tap loop (L0-resident body), 5 CTAs/SM.

#define IMG 256
#define SST 72                             // stride for BOTH smem copies
#define ROWS_SM 72                         // 64 + 8 halo
#define COPY_FLOATS (ROWS_SM * SST)        // 5184
#define SMEM_BYTES (2 * COPY_FLOATS * 4)

__device__ unsigned long long d_kpack[81];

__device__ __forceinline__ unsigned long long pack2(float lo, float hi) {
    unsigned long long r;
    asm("mov.b64 %0, {%1, %2};" : "=l"(r) : "f"(lo), "f"(hi));
    return r;
}

__device__ __forceinline__ void ffma2(unsigned long long& d,
                                      unsigned long long a,
                                      unsigned long long b) {
    asm("fma.rn.f32x2 %0, %1, %2, %0;" : "+l"(d) : "l"(a), "l"(b));
}

__global__ void pack_kernel(const float* __restrict__ K) {
    int i = threadIdx.x;
    if (i < 81) {
        float v = K[i];
        d_kpack[i] = pack2(v, v);
    }
}

__global__ __launch_bounds__(128, 5)
void conv9x9_kernel(const float* __restrict__ X,
                    float* __restrict__ out) {
    extern __shared__ float smem[];
    float* xe  = smem;                     // aligned copy
    float* xof = smem + COPY_FLOATS;       // shifted-by-one copy (stride 72)

    const int bx   = blockIdx.x;
    const int img  = bx >> 4;              // 2048 images
    const int t16  = bx & 15;              // 4x4 tiles of 64x64
    const int row0 = (t16 >> 2) * 64;
    const int col0 = (t16 & 3) * 64;

    const float* __restrict__ Xi = X + (size_t)img * (IMG * IMG);
    const int tid = threadIdx.x;

    // Stage tile (4-halo, zero-padded) into both copies.
    #pragma unroll 4
    for (int idx = tid; idx < COPY_FLOATS; idx += 128) {
        int r  = idx / SST;
        int c  = idx - r * SST;
        int gr = row0 - 4 + r;
        int gc = col0 - 4 + c;
        float v = 0.0f;
        if ((unsigned)gr < IMG && (unsigned)gc < IMG)
            v = Xi[gr * IMG + gc];
        xe[idx] = v;
        if (c >= 1 && c <= 71)
            xof[r * SST + (c - 1)] = v;    // orig cols 1..71 -> xof 0..70
    }
    __syncthreads();

    const int cg    = tid & 31;            // 32 colpairs: cols 2cg, 2cg+1
    const int rg    = tid >> 5;            // 4 rowgroups x 16 rows
    const int jb    = 2 * cg;              // even
    const int rbase = rg * 16;

    unsigned long long acc[16];
    #pragma unroll
    for (int i = 0; i < 16; ++i) acc[i] = 0ull;

    // Runtime loop over the 9 horizontal taps; ~4KB body, L0-resident.
    #pragma unroll 1
    for (int g = 0; g < 9; ++g) {
        // Pre-packed {k,k} coefficients for this tap: 9 uniform LDG.64.
        unsigned long long kr[9];
        #pragma unroll
        for (int u = 0; u < 9; ++u)
            kr[u] = __ldg(&d_kpack[u * 9 + g]);

        // Parity-resolved base for this tap's packed window.
        const float* base = (g & 1) ? &xof[rbase * SST + jb + g - 1]
                                    : &xe [rbase * SST + jb + g];

        // Depth-3 rotating pipeline: load t+2 before computing t.
        unsigned long long P[3];
        P[0] = *(const unsigned long long*)(base);
        P[1] = *(const unsigned long long*)(base + SST);
        #pragma unroll
        for (int t = 0; t < 24; ++t) {
            if (t + 2 < 24)
                P[(t + 2) % 3] =
                    *(const unsigned long long*)(base + (t + 2) * SST);
            const unsigned long long Pc = P[t % 3];
            #pragma unroll
            for (int u = 0; u < 9; ++u) {
                const int o = t - u;       // output row in chain
                if (o >= 0 && o < 16)
                    ffma2(acc[o], Pc, kr[u]);
            }
        }
    }

    float* __restrict__ Oi = out + (size_t)img * (IMG * IMG);
    #pragma unroll
    for (int o = 0; o < 16; ++o) {
        float lo, hi;
        asm("mov.b64 {%0, %1}, %2;" : "=f"(lo), "=f"(hi) : "l"(acc[o]));
        *(float2*)&Oi[(size_t)(row0 + rbase + o) * IMG + col0 + jb] =
            make_float2(lo, hi);
    }
}

extern "C" void kernel_launch(void* const* d_in, const int* in_sizes, int n_in,
                              void* d_out, int out_size) {
    const float* X = (const float*)d_in[0];
    const float* K = (const float*)d_in[1];
    if (n_in >= 2 && in_sizes[0] == 81) {  // metadata-order safety
        const float* t = X; X = K; K = t;
    }
    pack_kernel<<<1, 128>>>(K);
    cudaFuncSetAttribute(conv9x9_kernel,
                         cudaFuncAttributeMaxDynamicSharedMemorySize,
                         SMEM_BYTES);
    conv9x9_kernel<<<32768, 128, SMEM_BYTES>>>(X, (float*)d_out);
}

// round 9
// speedup vs baseline: 1.2082x; 1.2082x over previous
#include <cuda_runtime.h>
#include <cstdint>

// Depthwise 9x9 conv, stride 1, pad 4. X:(32,64,256,256) fp32, one shared kernel.
// R8: R6 base (best) + two isolated fixes:
//  - coefficients pre-packed {k,k} on device, then copied into __constant__
//    (D2D memcpy node, graph-capturable): per-tap setup = 9 bare LDC.64 on the
//    constant port -> no LDG scoreboard stalls (R7's bug), no pack MOVs (R6's
//    alu overhead).
//  - depth-3 rotating pipeline P[3]: each LDS leads its first consumer by
//    ~20 issue slots, covering smem latency (29cy) with margin.
// Unchanged: 128-thr CTA, thread = 2 cols x 16 rows, 64x64 tile, dual shifted
// stride-72 smem copies (any parity window = one conflict-free LDS.64),
// runtime tap loop (~4KB body, L0-resident), 5 CTAs/SM.

#define IMG 256
#define SST 72                             // stride for BOTH smem copies
#define ROWS_SM 72                         // 64 + 8 halo
#define COPY_FLOATS (ROWS_SM * SST)        // 5184
#define SMEM_BYTES (2 * COPY_FLOATS * 4)

__device__ unsigned long long d_kstage[81];
__constant__ unsigned long long cKpack[81];

__device__ __forceinline__ unsigned long long pack2(float lo, float hi) {
    unsigned long long r;
    asm("mov.b64 %0, {%1, %2};" : "=l"(r) : "f"(lo), "f"(hi));
    return r;
}

__device__ __forceinline__ void ffma2(unsigned long long& d,
                                      unsigned long long a,
                                      unsigned long long b) {
    asm("fma.rn.f32x2 %0, %1, %2, %0;" : "+l"(d) : "l"(a), "l"(b));
}

__global__ void pack_kernel(const float* __restrict__ K) {
    int i = threadIdx.x;
    if (i < 81) {
        float v = K[i];
        d_kstage[i] = pack2(v, v);
    }
}

__global__ __launch_bounds__(128, 5)
void conv9x9_kernel(const float* __restrict__ X,
                    float* __restrict__ out) {
    extern __shared__ float smem[];
    float* xe  = smem;                     // aligned copy
    float* xof = smem + COPY_FLOATS;       // shifted-by-one copy (stride 72)

    const int bx   = blockIdx.x;
    const int img  = bx >> 4;              // 2048 images
    const int t16  = bx & 15;              // 4x4 tiles of 64x64
    const int row0 = (t16 >> 2) * 64;
    const int col0 = (t16 & 3) * 64;

    const float* __restrict__ Xi = X + (size_t)img * (IMG * IMG);
    const int tid = threadIdx.x;

    // Stage tile (4-halo, zero-padded) into both copies.
    #pragma unroll 4
    for (int idx = tid; idx < COPY_FLOATS; idx += 128) {
        int r  = idx / SST;
        int c  = idx - r * SST;
        int gr = row0 - 4 + r;
        int gc = col0 - 4 + c;
        float v = 0.0f;
        if ((unsigned)gr < IMG && (unsigned)gc < IMG)
            v = Xi[gr * IMG + gc];
        xe[idx] = v;
        if (c >= 1 && c <= 71)
            xof[r * SST + (c - 1)] = v;    // orig cols 1..71 -> xof 0..70
    }
    __syncthreads();

    const int cg    = tid & 31;            // 32 colpairs: cols 2cg, 2cg+1
    const int rg    = tid >> 5;            // 4 rowgroups x 16 rows
    const int jb    = 2 * cg;              // even
    const int rbase = rg * 16;

    unsigned long long acc[16];
    #pragma unroll
    for (int i = 0; i < 16; ++i) acc[i] = 0ull;

    // Runtime loop over the 9 horizontal taps; small body, L0-resident.
    #pragma unroll 1
    for (int g = 0; g < 9; ++g) {
        // Pre-packed {k,k} coefficients for this tap: 9 bare LDC.64.
        unsigned long long kr[9];
        #pragma unroll
        for (int u = 0; u < 9; ++u)
            kr[u] = cKpack[u * 9 + g];

        // Parity-resolved base for this tap's packed window.
        const float* base = (g & 1) ? &xof[rbase * SST + jb + g - 1]
                                    : &xe [rbase * SST + jb + g];

        // Depth-3 rotating pipeline: load t+2 before computing t.
        unsigned long long P[3];
        P[0] = *(const unsigned long long*)(base);
        P[1] = *(const unsigned long long*)(base + SST);
        #pragma unroll
        for (int t = 0; t < 24; ++t) {
            if (t + 2 < 24)
                P[(t + 2) % 3] =
                    *(const unsigned long long*)(base + (t + 2) * SST);
            const unsigned long long Pc = P[t % 3];
            #pragma unroll
            for (int u = 0; u < 9; ++u) {
                const int o = t - u;       // output row in chain
                if (o >= 0 && o < 16)
                    ffma2(acc[o], Pc, kr[u]);
            }
        }
    }

    float* __restrict__ Oi = out + (size_t)img * (IMG * IMG);
    #pragma unroll
    for (int o = 0; o < 16; ++o) {
        float lo, hi;
        asm("mov.b64 {%0, %1}, %2;" : "=f"(lo), "=f"(hi) : "l"(acc[o]));
        *(float2*)&Oi[(size_t)(row0 + rbase + o) * IMG + col0 + jb] =
            make_float2(lo, hi);
    }
}

extern "C" void kernel_launch(void* const* d_in, const int* in_sizes, int n_in,
                              void* d_out, int out_size) {
    const float* X = (const float*)d_in[0];
    const float* K = (const float*)d_in[1];
    if (n_in >= 2 && in_sizes[0] == 81) {  // metadata-order safety
        const float* t = X; X = K; K = t;
    }
    pack_kernel<<<1, 128>>>(K);
    void* stage_ptr = nullptr;
    cudaGetSymbolAddress(&stage_ptr, d_kstage);
    cudaMemcpyToSymbolAsync(cKpack, stage_ptr, 81 * sizeof(unsigned long long),
                            0, cudaMemcpyDeviceToDevice, 0);
    cudaFuncSetAttribute(conv9x9_kernel,
                         cudaFuncAttributeMaxDynamicSharedMemorySize,
                         SMEM_BYTES);
    conv9x9_kernel<<<32768, 128, SMEM_BYTES>>>(X, (float*)d_out);
}

// round 11
// speedup vs baseline: 1.3679x; 1.1322x over previous
#include <cuda_runtime.h>
#include <cstdint>

// Depthwise 9x9 conv, stride 1, pad 4. X:(32,64,256,256) fp32, one shared kernel.
// R10: R9 (vectorized float4 staging) with the shifted-copy index fixed:
// orig col c -> xof[c-1], so v.w (orig ce+3) goes to xof[ce+2] (was ce+3).
//  - pad=4 == vector width and col0-4 is 16B-aligned => every halo LDG.128 is
//    fully in-bounds or fully OOB: one predicate per float4, no partials.
//  - (r,c4) maintained incrementally (128 = 7*18+2): ~3 alu/iter, no divides.
// Hot loop unchanged from R8/R6 best: 128-thr CTA, thread = 2 cols x 16 rows,
// 64x64 tile, dual shifted stride-72 smem copies (conflict-free LDS.64 for
// both parities), runtime tap loop with LDC.64 packed coeffs, depth-3
// pipeline, 5 CTAs/SM.

#define IMG 256
#define SST 72                             // stride for BOTH smem copies
#define ROWS_SM 72                         // 64 + 8 halo
#define COPY_FLOATS (ROWS_SM * SST)        // 5184
#define NVEC (ROWS_SM * 18)                // 1296 float4s per tile
#define SMEM_BYTES (2 * COPY_FLOATS * 4)

__device__ unsigned long long d_kstage[81];
__constant__ unsigned long long cKpack[81];

__device__ __forceinline__ unsigned long long pack2(float lo, float hi) {
    unsigned long long r;
    asm("mov.b64 %0, {%1, %2};" : "=l"(r) : "f"(lo), "f"(hi));
    return r;
}

__device__ __forceinline__ void ffma2(unsigned long long& d,
                                      unsigned long long a,
                                      unsigned long long b) {
    asm("fma.rn.f32x2 %0, %1, %2, %0;" : "+l"(d) : "l"(a), "l"(b));
}

__global__ void pack_kernel(const float* __restrict__ K) {
    int i = threadIdx.x;
    if (i < 81) {
        float v = K[i];
        d_kstage[i] = pack2(v, v);
    }
}

__global__ __launch_bounds__(128, 5)
void conv9x9_kernel(const float* __restrict__ X,
                    float* __restrict__ out) {
    extern __shared__ float smem[];
    float* xe  = smem;                     // aligned copy
    float* xof = smem + COPY_FLOATS;       // shifted-by-one copy (stride 72)

    const int bx   = blockIdx.x;
    const int img  = bx >> 4;              // 2048 images
    const int t16  = bx & 15;              // 4x4 tiles of 64x64
    const int row0 = (t16 >> 2) * 64;
    const int col0 = (t16 & 3) * 64;

    const float* __restrict__ Xi = X + (size_t)img * (IMG * IMG);
    const int tid = threadIdx.x;

    // ---- Vectorized staging: 1296 float4s, fully-in/fully-out predicates ----
    {
        int r  = tid / 18;                 // one small division at entry
        int c4 = tid - r * 18;
        int idx = tid;
        #pragma unroll 1
        while (idx < NVEC) {
            const int gr  = row0 - 4 + r;
            const int gc0 = col0 - 4 + (c4 << 2);
            float4 v = make_float4(0.f, 0.f, 0.f, 0.f);
            if ((unsigned)gr < IMG && (unsigned)gc0 < IMG)   // whole-vec check
                v = *(const float4*)&Xi[gr * IMG + gc0];

            const int ce = (c4 << 2);
            // aligned copy: orig cols ce..ce+3
            *(float4*)&xe[r * SST + ce] = v;
            // shifted copy: orig col c -> xof[c-1]
            *(float2*)&xof[r * SST + ce] = make_float2(v.y, v.z);  // ce, ce+1
            if (ce > 0) xof[r * SST + ce - 1] = v.x;               // ce-1
            xof[r * SST + ce + 2] = v.w;                           // ce+2

            idx += 128;                    // 128 = 7*18 + 2
            r  += 7;
            c4 += 2;
            if (c4 >= 18) { c4 -= 18; r += 1; }
        }
    }
    __syncthreads();

    const int cg    = tid & 31;            // 32 colpairs: cols 2cg, 2cg+1
    const int rg    = tid >> 5;            // 4 rowgroups x 16 rows
    const int jb    = 2 * cg;              // even
    const int rbase = rg * 16;

    unsigned long long acc[16];
    #pragma unroll
    for (int i = 0; i < 16; ++i) acc[i] = 0ull;

    // Runtime loop over the 9 horizontal taps; small body, L0-resident.
    #pragma unroll 1
    for (int g = 0; g < 9; ++g) {
        // Pre-packed {k,k} coefficients for this tap: 9 bare LDC.64.
        unsigned long long kr[9];
        #pragma unroll
        for (int u = 0; u < 9; ++u)
            kr[u] = cKpack[u * 9 + g];

        // Parity-resolved base for this tap's packed window.
        const float* base = (g & 1) ? &xof[rbase * SST + jb + g - 1]
                                    : &xe [rbase * SST + jb + g];

        // Depth-3 rotating pipeline: load t+2 before computing t.
        unsigned long long P[3];
        P[0] = *(const unsigned long long*)(base);
        P[1] = *(const unsigned long long*)(base + SST);
        #pragma unroll
        for (int t = 0; t < 24; ++t) {
            if (t + 2 < 24)
                P[(t + 2) % 3] =
                    *(const unsigned long long*)(base + (t + 2) * SST);
            const unsigned long long Pc = P[t % 3];
            #pragma unroll
            for (int u = 0; u < 9; ++u) {
                const int o = t - u;       // output row in chain
                if (o >= 0 && o < 16)
                    ffma2(acc[o], Pc, kr[u]);
            }
        }
    }

    float* __restrict__ Oi = out + (size_t)img * (IMG * IMG);
    #pragma unroll
    for (int o = 0; o < 16; ++o) {
        float lo, hi;
        asm("mov.b64 {%0, %1}, %2;" : "=f"(lo), "=f"(hi) : "l"(acc[o]));
        *(float2*)&Oi[(size_t)(row0 + rbase + o) * IMG + col0 + jb] =
            make_float2(lo, hi);
    }
}

extern "C" void kernel_launch(void* const* d_in, const int* in_sizes, int n_in,
                              void* d_out, int out_size) {
    const float* X = (const float*)d_in[0];
    const float* K = (const float*)d_in[1];
    if (n_in >= 2 && in_sizes[0] == 81) {  // metadata-order safety
        const float* t = X; X = K; K = t;
    }
    pack_kernel<<<1, 128>>>(K);
    void* stage_ptr = nullptr;
    cudaGetSymbolAddress(&stage_ptr, d_kstage);
    cudaMemcpyToSymbolAsync(cKpack, stage_ptr, 81 * sizeof(unsigned long long),
                            0, cudaMemcpyDeviceToDevice, 0);
    cudaFuncSetAttribute(conv9x9_kernel,
                         cudaFuncAttributeMaxDynamicSharedMemorySize,
                         SMEM_BYTES);
    conv9x9_kernel<<<32768, 128, SMEM_BYTES>>>(X, (float*)d_out);
}

// round 12
// speedup vs baseline: 1.5573x; 1.1384x over previous
#include <cuda_runtime.h>
#include <cstdint>

// Depthwise 9x9 conv, stride 1, pad 4. X:(32,64,256,256) fp32, one shared kernel.
// R11: IMAGE-PAIR f32x2 packing. Each f32x2 lane pair = (imgA, imgB) at the
// same (i,j), so every tap offset is identical in both lanes:
//  - NO shifted smem copy, NO window-parity problem: any window is one
//    8B-aligned LDS.64 from a single interleaved tile.
//  - smem/CTA = 23KB covering 2 images of outputs -> 8 CTAs/SM (32 warps).
//  - staging: float2 per image -> one STS.128 of (ax,bx,ay,by), contiguous.
// Main loop structure unchanged from best: runtime tap loop, LDC.64 packed
// {k,k} coeffs, depth-3 rotating pipeline, C=16 chains, conflict-free LDS.64.
// CTA 128 thr = 64 cols x 2 rowgroups x 16 rows -> 64x32 tile x 2 images.

#define IMG 256
#define IMGSZ (IMG * IMG)
#define ICOLS 72                           // halo cols per image tile
#define SROW 144                           // interleaved floats per smem row
#define SROWS 40                           // 32 + 8 halo rows
#define NUNIT (SROWS * 36)                 // 1440 float2-pair units
#define SMEM_BYTES (SROWS * SROW * 4)      // 23040

__device__ unsigned long long d_kstage[81];
__constant__ unsigned long long cKpack[81];

__device__ __forceinline__ unsigned long long pack2(float lo, float hi) {
    unsigned long long r;
    asm("mov.b64 %0, {%1, %2};" : "=l"(r) : "f"(lo), "f"(hi));
    return r;
}

__device__ __forceinline__ void ffma2(unsigned long long& d,
                                      unsigned long long a,
                                      unsigned long long b) {
    asm("fma.rn.f32x2 %0, %1, %2, %0;" : "+l"(d) : "l"(a), "l"(b));
}

__global__ void pack_kernel(const float* __restrict__ K) {
    int i = threadIdx.x;
    if (i < 81) {
        float v = K[i];
        d_kstage[i] = pack2(v, v);
    }
}

__global__ __launch_bounds__(128, 8)
void conv9x9_kernel(const float* __restrict__ X,
                    float* __restrict__ out) {
    extern __shared__ float smem[];

    const int bx    = blockIdx.x;
    const int pair  = bx >> 5;             // 1024 image pairs
    const int t32   = bx & 31;             // 4 colstrips x 8 rowstrips
    const int row0  = (t32 >> 2) * 32;
    const int col0  = (t32 & 3) * 64;

    const float* __restrict__ XA = X + (size_t)(2 * pair)     * IMGSZ;
    const float* __restrict__ XB = X + (size_t)(2 * pair + 1) * IMGSZ;
    const int tid = threadIdx.x;

    // ---- Stage interleaved tile: unit = (row r, float2-col c2) ----
    {
        int r  = tid / 36;
        int c2 = tid - r * 36;
        int idx = tid;
        #pragma unroll 1
        while (idx < NUNIT) {
            const int gr  = row0 - 4 + r;
            const int gc0 = col0 - 4 + 2 * c2;   // even; pair fully in or out
            float2 a = make_float2(0.f, 0.f);
            float2 b = make_float2(0.f, 0.f);
            if ((unsigned)gr < IMG && (unsigned)gc0 < IMG) {
                a = *(const float2*)&XA[gr * IMG + gc0];
                b = *(const float2*)&XB[gr * IMG + gc0];
            }
            // interleaved: orig col c -> smem floats (2c, 2c+1) = (A, B)
            *(float4*)&smem[r * SROW + 4 * c2] =
                make_float4(a.x, b.x, a.y, b.y);

            idx += 128;                    // 128 = 3*36 + 20
            r  += 3;
            c2 += 20;
            if (c2 >= 36) { c2 -= 36; r += 1; }
        }
    }
    __syncthreads();

    const int j     = tid & 63;            // column within tile (one per thread)
    const int rg    = tid >> 6;            // 2 rowgroups x 16 rows
    const int rbase = rg * 16;

    unsigned long long acc[16];
    #pragma unroll
    for (int i = 0; i < 16; ++i) acc[i] = 0ull;

    // Runtime loop over the 9 horizontal taps; small body, L0-resident.
    #pragma unroll 1
    for (int g = 0; g < 9; ++g) {
        // Pre-packed {k,k} coefficients for this tap: 9 bare LDC.64.
        unsigned long long kr[9];
        #pragma unroll
        for (int u = 0; u < 9; ++u)
            kr[u] = cKpack[u * 9 + g];

        // Window base: interleaved col (j+g) -> float offset 2*(j+g). 8B-aligned.
        const float* base = &smem[rbase * SROW + 2 * (j + g)];

        // Depth-3 rotating pipeline: load t+2 before computing t.
        unsigned long long P[3];
        P[0] = *(const unsigned long long*)(base);
        P[1] = *(const unsigned long long*)(base + SROW);
        #pragma unroll
        for (int t = 0; t < 24; ++t) {
            if (t + 2 < 24)
                P[(t + 2) % 3] =
                    *(const unsigned long long*)(base + (t + 2) * SROW);
            const unsigned long long Pc = P[t % 3];
            #pragma unroll
            for (int u = 0; u < 9; ++u) {
                const int o = t - u;       // output row in chain
                if (o >= 0 && o < 16)
                    ffma2(acc[o], Pc, kr[u]);
            }
        }
    }

    float* __restrict__ OA = out + (size_t)(2 * pair)     * IMGSZ;
    float* __restrict__ OB = out + (size_t)(2 * pair + 1) * IMGSZ;
    #pragma unroll
    for (int o = 0; o < 16; ++o) {
        float lo, hi;
        asm("mov.b64 {%0, %1}, %2;" : "=f"(lo), "=f"(hi) : "l"(acc[o]));
        const int off = (row0 + rbase + o) * IMG + col0 + j;
        OA[off] = lo;
        OB[off] = hi;
    }
}

extern "C" void kernel_launch(void* const* d_in, const int* in_sizes, int n_in,
                              void* d_out, int out_size) {
    const float* X = (const float*)d_in[0];
    const float* K = (const float*)d_in[1];
    if (n_in >= 2 && in_sizes[0] == 81) {  // metadata-order safety
        const float* t = X; X = K; K = t;
    }
    pack_kernel<<<1, 128>>>(K);
    void* stage_ptr = nullptr;
    cudaGetSymbolAddress(&stage_ptr, d_kstage);
    cudaMemcpyToSymbolAsync(cKpack, stage_ptr, 81 * sizeof(unsigned long long),
                            0, cudaMemcpyDeviceToDevice, 0);
    cudaFuncSetAttribute(conv9x9_kernel,
                         cudaFuncAttributeMaxDynamicSharedMemorySize,
                         SMEM_BYTES);
    conv9x9_kernel<<<32768, 128, SMEM_BYTES>>>(X, (float*)d_out);
}